// round 1
// baseline (speedup 1.0000x reference)
#include <cuda_runtime.h>
#include <math.h>

#define B_ 32
#define S_ 8192
#define CIN_ 2
#define COUT_ 1
#define W_ 64
#define M_ 16
#define P_ 24
#define NROWS (B_*W_)      /* 2048 */
#define NSPLIT 16

// -------- scratch (device globals; no allocation allowed) --------
__device__ float g_h[NROWS * S_];            // 64 MB, (b*W + w)*S + s
__device__ float g_F[S_ * 32];               // [s][j]: j<16 cos(2pi j s/S), j>=16 sin
__device__ float g_part[NSPLIT * NROWS * 32];// split-K partials of fwd DFT
__device__ float g_ar[B_ * W_ * M_];         // scaled spectral output (real)
__device__ float g_ai[B_ * W_ * M_];         // scaled spectral output (imag)

// ---------------------------------------------------------------
// DFT basis table: exact angle via double sincos.
__global__ void k_compute_F() {
    int idx = blockIdx.x * blockDim.x + threadIdx.x;
    if (idx >= S_ * M_) return;
    int s = idx / M_, k = idx % M_;
    int r = (s * k) % S_;
    double th = (2.0 * 3.14159265358979323846 / (double)S_) * (double)r;
    double c, sn;
    sincos(th, &sn, &c);
    g_F[s * 32 + k]      = (float)c;
    g_F[s * 32 + 16 + k] = (float)sn;
}

// ---------------------------------------------------------------
// lift: h[b,w,s] = x[b,s,0]*fc0_w[w,0] + x[b,s,1]*fc0_w[w,1] + fc0_b[w]
__global__ __launch_bounds__(256) void k_lift(
    const float* __restrict__ x, const float* __restrict__ fc0_w,
    const float* __restrict__ fc0_b)
{
    int s = blockIdx.x * 256 + threadIdx.x;
    int b = blockIdx.y;
    float x0 = x[(b * S_ + s) * 2 + 0];
    float x1 = x[(b * S_ + s) * 2 + 1];
#pragma unroll
    for (int w = 0; w < W_; w++) {
        float v = x0 * __ldg(&fc0_w[w * 2]) + x1 * __ldg(&fc0_w[w * 2 + 1]) + __ldg(&fc0_b[w]);
        g_h[(b * W_ + w) * S_ + s] = v;
    }
}

// ---------------------------------------------------------------
// fwd DFT: C[2048,32] = H[2048,8192] x F[8192,32], split-K into 16 partials.
// block: 128 threads, tile 128 rows x 32 cols, thread tile 8x4.
#define KT 32
__global__ __launch_bounds__(128) void k_dft_fwd() {
    __shared__ float sA[128][33];
    __shared__ float sB[KT][32];
    int tid = threadIdx.x;
    int tx = tid & 7;        // col group (4 cols each)
    int ty = tid >> 3;       // row group (8 rows each), 0..15
    int row0 = blockIdx.x * 128;
    int split = blockIdx.y;

    float acc[8][4];
#pragma unroll
    for (int r = 0; r < 8; r++)
#pragma unroll
        for (int c = 0; c < 4; c++) acc[r][c] = 0.f;

    for (int kt = 0; kt < (S_ / NSPLIT) / KT; kt++) {
        int k0 = (split * ((S_ / NSPLIT) / KT) + kt) * KT;
#pragma unroll
        for (int it = 0; it < 32; it++) {
            int idx = tid + 128 * it;
            int m = idx >> 5, kk = idx & 31;
            sA[m][kk] = g_h[(row0 + m) * S_ + k0 + kk];
        }
#pragma unroll
        for (int it = 0; it < 8; it++) {
            int idx = tid + 128 * it;
            int kk = idx >> 5, n = idx & 31;
            sB[kk][n] = g_F[(k0 + kk) * 32 + n];
        }
        __syncthreads();
#pragma unroll
        for (int kk = 0; kk < KT; kk++) {
            float a[8], bb[4];
#pragma unroll
            for (int r = 0; r < 8; r++) a[r] = sA[ty + 16 * r][kk];
#pragma unroll
            for (int c = 0; c < 4; c++) bb[c] = sB[kk][tx + 8 * c];
#pragma unroll
            for (int r = 0; r < 8; r++)
#pragma unroll
                for (int c = 0; c < 4; c++) acc[r][c] += a[r] * bb[c];
        }
        __syncthreads();
    }
#pragma unroll
    for (int r = 0; r < 8; r++)
#pragma unroll
        for (int c = 0; c < 4; c++)
            g_part[(split * NROWS + row0 + ty + 16 * r) * 32 + tx + 8 * c] = acc[r][c];
}

// ---------------------------------------------------------------
// spectral multiply: reduce split-K partials -> xf, then
// of[b,o,k] = sum_i xf[b,i,k]*w[i,o,k]  (complex), store scaled by c_k/S.
// grid (B_, 8), 128 threads: block handles 8 outputs channels x 16 modes.
__global__ __launch_bounds__(128) void k_specmul(
    const float* __restrict__ wr, const float* __restrict__ wi, int l)
{
    __shared__ float sxr[W_][16];
    __shared__ float sxi[W_][16];
    int b = blockIdx.x;
    int o0 = blockIdx.y * 8;
    int tid = threadIdx.x;

    for (int e = tid; e < W_ * 32; e += 128) {
        int i = e >> 5, j = e & 31;
        float s = 0.f;
#pragma unroll
        for (int sp = 0; sp < NSPLIT; sp++)
            s += g_part[(sp * NROWS + b * W_ + i) * 32 + j];
        if (j < 16) sxr[i][j] = s;
        else        sxi[i][j - 16] = -s;   // rfft: imag = -sum(h*sin)
    }
    __syncthreads();

    int o = o0 + (tid >> 4);
    int k = tid & 15;
    float accr = 0.f, acci = 0.f;
#pragma unroll
    for (int i = 0; i < W_; i++) {
        float xr = sxr[i][k], xi = sxi[i][k];
        float wrr = __ldg(&wr[((l * W_ + i) * W_ + o) * M_ + k]);
        float wii = __ldg(&wi[((l * W_ + i) * W_ + o) * M_ + k]);
        accr += xr * wrr - xi * wii;
        acci += xr * wii + xi * wrr;
    }
    float sc = (k == 0 ? 1.0f : 2.0f) / (float)S_;  // irfft fold: Re X0 + 2*sum Re(...)
    g_ar[(b * W_ + o) * M_ + k] = accr * sc;
    g_ai[(b * W_ + o) * M_ + k] = acci * sc;
}

// ---------------------------------------------------------------
// layer update (in-place): h[b,o,s] = relu?( irfft16(of)[o,s] + sum_i pw[o,i]*h[b,i,s] + pw_b[o] )
// block: (b, 128-wide s tile), 256 threads, thread tile 8 o x 4 s.
__global__ __launch_bounds__(256) void k_layer(
    const float* __restrict__ pw_w, const float* __restrict__ pw_b,
    int l, int do_relu)
{
    extern __shared__ float sm[];
    float* sh  = sm;                 // 64*128
    float* sF  = sh + 64 * 128;      // 128*33
    float* sW  = sF + 128 * 33;      // 64*64
    float* sar = sW + 64 * 64;       // 64*16
    float* sai = sar + 64 * 16;      // 64*16
    float* sb  = sai + 64 * 16;      // 64

    int b = blockIdx.y;
    int s0 = blockIdx.x * 128;
    int tid = threadIdx.x;
    int tx = tid & 31;   // s lane
    int ty = tid >> 5;   // o group (8)

    for (int e = tid; e < 64 * 128; e += 256) {
        int w = e >> 7, s = e & 127;
        sh[w * 128 + s] = g_h[(b * W_ + w) * S_ + s0 + s];
    }
    for (int e = tid; e < 128 * 32; e += 256) {
        int s = e >> 5, j = e & 31;
        sF[s * 33 + j] = g_F[(s0 + s) * 32 + j];
    }
    for (int e = tid; e < 64 * 64; e += 256)
        sW[e] = pw_w[l * W_ * W_ + e];
    for (int e = tid; e < 64 * 16; e += 256) {
        sar[e] = g_ar[(b * W_) * M_ + e];
        sai[e] = g_ai[(b * W_) * M_ + e];
    }
    if (tid < 64) sb[tid] = pw_b[l * W_ + tid];
    __syncthreads();

    float acc[8][4];
#pragma unroll
    for (int r = 0; r < 8; r++)
#pragma unroll
        for (int c = 0; c < 4; c++) acc[r][c] = 0.f;

    // pointwise conv
#pragma unroll 4
    for (int i = 0; i < W_; i++) {
        float hv[4], wv[8];
#pragma unroll
        for (int c = 0; c < 4; c++) hv[c] = sh[i * 128 + tx + 32 * c];
#pragma unroll
        for (int r = 0; r < 8; r++) wv[r] = sW[(ty + 8 * r) * 64 + i];
#pragma unroll
        for (int r = 0; r < 8; r++)
#pragma unroll
            for (int c = 0; c < 4; c++) acc[r][c] += wv[r] * hv[c];
    }
    // irfft from 16 modes
#pragma unroll
    for (int k = 0; k < M_; k++) {
        float fc[4], fs[4], arr[8], aii[8];
#pragma unroll
        for (int c = 0; c < 4; c++) {
            fc[c] = sF[(tx + 32 * c) * 33 + k];
            fs[c] = sF[(tx + 32 * c) * 33 + 16 + k];
        }
#pragma unroll
        for (int r = 0; r < 8; r++) {
            arr[r] = sar[(ty + 8 * r) * 16 + k];
            aii[r] = sai[(ty + 8 * r) * 16 + k];
        }
#pragma unroll
        for (int r = 0; r < 8; r++)
#pragma unroll
            for (int c = 0; c < 4; c++)
                acc[r][c] += arr[r] * fc[c] - aii[r] * fs[c];
    }
#pragma unroll
    for (int r = 0; r < 8; r++) {
        int o = ty + 8 * r;
        float bo = sb[o];
#pragma unroll
        for (int c = 0; c < 4; c++) {
            float v = acc[r][c] + bo;
            if (do_relu) v = fmaxf(v, 0.f);
            g_h[(b * W_ + o) * S_ + s0 + tx + 32 * c] = v;
        }
    }
}

// ---------------------------------------------------------------
// head: per (b, 64-wide s tile):
//   y = fc1_w @ h + fc1_b; u = relu(y)*fc2_w; tc = ica_w @ u + ica_b; out = sum_p tc
__global__ __launch_bounds__(256) void k_head(
    const float* __restrict__ fc1_w, const float* __restrict__ fc1_b,
    const float* __restrict__ fc2_w, const float* __restrict__ ica_w,
    const float* __restrict__ ica_b, float* __restrict__ out,
    float* __restrict__ tc)
{
    extern __shared__ float sm[];
    float* sh   = sm;                   // 64*64
    float* sfc1 = sh + 64 * 64;         // 128*65
    float* sU   = sfc1 + 128 * 65;      // 128*65
    float* sica = sU + 128 * 65;        // 24*128
    float* sTc  = sica + 24 * 128;      // 64*24
    float* sb1  = sTc + 64 * 24;        // 128
    float* sf2  = sb1 + 128;            // 128
    float* sib  = sf2 + 128;            // 24
    __shared__ float sred[4][64];

    int b = blockIdx.y;
    int s0 = blockIdx.x * 64;
    int tid = threadIdx.x;

    for (int e = tid; e < 64 * 64; e += 256) {
        int w = e >> 6, s = e & 63;
        sh[w * 64 + s] = g_h[(b * W_ + w) * S_ + s0 + s];
    }
    for (int e = tid; e < 128 * 64; e += 256) {
        int j = e >> 6, w = e & 63;
        sfc1[j * 65 + w] = fc1_w[e];
    }
    for (int e = tid; e < 24 * 128; e += 256) sica[e] = ica_w[e];
    if (tid < 128) { sb1[tid] = fc1_b[tid]; sf2[tid] = fc2_w[tid]; }
    if (tid < 24)  sib[tid] = ica_b[tid];
    __syncthreads();

    // GEMM1: Y[128 j][64 s], thread tile 8j x 4s
    {
        int tx = tid & 15;    // s lane
        int ty = tid >> 4;    // j group, 0..15
        float acc[8][4];
#pragma unroll
        for (int r = 0; r < 8; r++)
#pragma unroll
            for (int c = 0; c < 4; c++) acc[r][c] = 0.f;
#pragma unroll 4
        for (int w = 0; w < 64; w++) {
            float hv[4], fv[8];
#pragma unroll
            for (int c = 0; c < 4; c++) hv[c] = sh[w * 64 + tx + 16 * c];
#pragma unroll
            for (int r = 0; r < 8; r++) fv[r] = sfc1[(ty + 16 * r) * 65 + w];
#pragma unroll
            for (int r = 0; r < 8; r++)
#pragma unroll
                for (int c = 0; c < 4; c++) acc[r][c] += fv[r] * hv[c];
        }
#pragma unroll
        for (int r = 0; r < 8; r++) {
            int j = ty + 16 * r;
            float bj = sb1[j], f2 = sf2[j];
#pragma unroll
            for (int c = 0; c < 4; c++) {
                float u = fmaxf(acc[r][c] + bj, 0.f) * f2;
                sU[j * 65 + tx + 16 * c] = u;
            }
        }
    }
    __syncthreads();

    // GEMM2: tc[24 p][64 s]; thread: 1 s, 6 p (p = pq + 4q)
    {
        int s = tid & 63;
        int pq = tid >> 6;   // 0..3
        float a2[6];
#pragma unroll
        for (int q = 0; q < 6; q++) a2[q] = 0.f;
#pragma unroll 4
        for (int j = 0; j < 128; j++) {
            float uv = sU[j * 65 + s];
#pragma unroll
            for (int q = 0; q < 6; q++)
                a2[q] += sica[(pq + 4 * q) * 128 + j] * uv;
        }
        float psum = 0.f;
#pragma unroll
        for (int q = 0; q < 6; q++) {
            int p = pq + 4 * q;
            float v = a2[q] + sib[p];
            sTc[s * 24 + p] = v;
            psum += v;
        }
        sred[pq][s] = psum;
    }
    __syncthreads();

    float* tc_base = tc + (size_t)(b * S_ + s0) * P_;
    for (int e = tid; e < 64 * P_; e += 256) tc_base[e] = sTc[e];
    if (tid < 64)
        out[(size_t)b * S_ + s0 + tid] =
            sred[0][tid] + sred[1][tid] + sred[2][tid] + sred[3][tid];
}

// ---------------------------------------------------------------
extern "C" void kernel_launch(void* const* d_in, const int* in_sizes, int n_in,
                              void* d_out, int out_size) {
    (void)in_sizes; (void)n_in; (void)out_size;
    const float* x       = (const float*)d_in[0];
    const float* fc0_w   = (const float*)d_in[1];
    const float* fc0_b   = (const float*)d_in[2];
    const float* conv_wr = (const float*)d_in[3];
    const float* conv_wi = (const float*)d_in[4];
    const float* pw_w    = (const float*)d_in[5];
    const float* pw_b    = (const float*)d_in[6];
    const float* fc1_w   = (const float*)d_in[7];
    const float* fc1_b   = (const float*)d_in[8];
    const float* fc2_w   = (const float*)d_in[9];
    const float* ica_w   = (const float*)d_in[10];
    const float* ica_b   = (const float*)d_in[11];

    float* out = (float*)d_out;
    float* tc  = out + (size_t)B_ * S_ * COUT_;

    const int LAY_SMEM  = (64*128 + 128*33 + 64*64 + 64*16*2 + 64) * 4;       // 74496 B
    const int HEAD_SMEM = (64*64 + 128*65 + 128*65 + 24*128 + 64*24 + 280)*4; // 102496 B
    cudaFuncSetAttribute(k_layer, cudaFuncAttributeMaxDynamicSharedMemorySize, LAY_SMEM);
    cudaFuncSetAttribute(k_head,  cudaFuncAttributeMaxDynamicSharedMemorySize, HEAD_SMEM);

    k_compute_F<<<(S_ * M_ + 255) / 256, 256>>>();
    k_lift<<<dim3(S_ / 256, B_), 256>>>(x, fc0_w, fc0_b);

    for (int l = 0; l < 4; l++) {
        k_dft_fwd<<<dim3(NROWS / 128, NSPLIT), 128>>>();
        k_specmul<<<dim3(B_, 8), 128>>>(conv_wr, conv_wi, l);
        k_layer<<<dim3(S_ / 128, B_), 256, LAY_SMEM>>>(pw_w, pw_b, l, (l < 3) ? 1 : 0);
    }

    k_head<<<dim3(S_ / 64, B_), 256, HEAD_SMEM>>>(fc1_w, fc1_b, fc2_w, ica_w, ica_b, out, tc);
}

// round 5
// speedup vs baseline: 1.4182x; 1.4182x over previous
#include <cuda_runtime.h>
#include <math.h>

#define B_ 32
#define S_ 8192
#define CIN_ 2
#define COUT_ 1
#define W_ 64
#define M_ 16
#define P_ 24
#define NROWS (B_*W_)      /* 2048 */
#define NSPLIT 32

// -------- scratch (device globals; no allocation allowed) --------
__device__ float g_h[NROWS * S_];            // 64 MB, (b*W + w)*S + s
__device__ float g_F[S_ * 32];               // [s][j]: j<16 cos(2pi j s/S), j>=16 sin
__device__ float g_part[NSPLIT * NROWS * 32];// split-K partials of fwd DFT (8 MB)
__device__ float g_ar[B_ * W_ * M_];         // scaled spectral output (real)
__device__ float g_ai[B_ * W_ * M_];         // scaled spectral output (imag)

// ---------------------------------------------------------------
// DFT basis table via float sincospif (r/4096 is exact; ~2ulp accuracy).
__global__ void k_compute_F() {
    int idx = blockIdx.x * blockDim.x + threadIdx.x;
    if (idx >= S_ * M_) return;
    int s = idx / M_, k = idx % M_;
    int r = (s * k) % S_;
    float c, sn;
    sincospif((float)r / 4096.0f, &sn, &c);   // theta = pi * (2 s k / S)
    g_F[s * 32 + k]      = c;
    g_F[s * 32 + 16 + k] = sn;
}

// ---------------------------------------------------------------
// lift: h[b,w,s] = x[b,s,0]*fc0_w[w,0] + x[b,s,1]*fc0_w[w,1] + fc0_b[w]
__global__ __launch_bounds__(256) void k_lift(
    const float* __restrict__ x, const float* __restrict__ fc0_w,
    const float* __restrict__ fc0_b)
{
    int s = blockIdx.x * 256 + threadIdx.x;
    int b = blockIdx.y;
    float2 xv = *(const float2*)&x[(b * S_ + s) * 2];
#pragma unroll
    for (int w = 0; w < W_; w++) {
        float v = xv.x * __ldg(&fc0_w[w * 2]) + xv.y * __ldg(&fc0_w[w * 2 + 1]) + __ldg(&fc0_b[w]);
        g_h[(b * W_ + w) * S_ + s] = v;
    }
}

// ---------------------------------------------------------------
// fwd DFT: C[2048,32] = H[2048,8192] x F[8192,32], split-K into 32 partials.
// block: 256 threads, tile 256 rows x 32 cols, thread tile 8x4, float4 loads.
#define KT 32
#define DROWS 256
__global__ __launch_bounds__(256) void k_dft_fwd() {
    __shared__ float sA[DROWS * 36];
    __shared__ float sB[KT * 32];
    int tid = threadIdx.x;
    int tx = tid & 7;        // col group (4 cols each)
    int ty = tid >> 3;       // row group, 0..31 (rows ty + 32*r)
    int row0 = blockIdx.x * DROWS;
    int split = blockIdx.y;

    float acc[8][4];
#pragma unroll
    for (int r = 0; r < 8; r++)
#pragma unroll
        for (int c = 0; c < 4; c++) acc[r][c] = 0.f;

    const int KSPLIT = S_ / NSPLIT;   // 256
    for (int kt = 0; kt < KSPLIT / KT; kt++) {
        int k0 = split * KSPLIT + kt * KT;
        // sA: 256 rows x 32 cols as float4 (8 per thread)
        {
            int c4 = (tid & 7) * 4;
            int rb = tid >> 3;
#pragma unroll
            for (int it = 0; it < 8; it++) {
                int row = rb + 32 * it;
                float4 v = *(const float4*)&g_h[(size_t)(row0 + row) * S_ + k0 + c4];
                *(float4*)&sA[row * 36 + c4] = v;
            }
        }
        // sB: 32x32 floats, 1 float4 per thread
        {
            int j4 = (tid & 7) * 4;
            int kk = tid >> 3;
            *(float4*)&sB[kk * 32 + j4] = *(const float4*)&g_F[(k0 + kk) * 32 + j4];
        }
        __syncthreads();
#pragma unroll
        for (int kk = 0; kk < KT; kk++) {
            float a[8], bb[4];
#pragma unroll
            for (int r = 0; r < 8; r++) a[r] = sA[(ty + 32 * r) * 36 + kk];
#pragma unroll
            for (int c = 0; c < 4; c++) bb[c] = sB[kk * 32 + tx + 8 * c];
#pragma unroll
            for (int r = 0; r < 8; r++)
#pragma unroll
                for (int c = 0; c < 4; c++) acc[r][c] += a[r] * bb[c];
        }
        __syncthreads();
    }
#pragma unroll
    for (int r = 0; r < 8; r++)
#pragma unroll
        for (int c = 0; c < 4; c++)
            g_part[(size_t)(split * NROWS + row0 + ty + 32 * r) * 32 + tx + 8 * c] = acc[r][c];
}

// ---------------------------------------------------------------
// spectral multiply: one block per batch. Reduce partials ONCE into smem,
// then of[b,o,k] = sum_i xf[b,i,k]*w[i,o,k] (complex), scaled by c_k/S.
__global__ __launch_bounds__(256) void k_specmul(
    const float* __restrict__ wr, const float* __restrict__ wi, int l)
{
    __shared__ float sxr[W_ * 16];
    __shared__ float sxi[W_ * 16];
    int b = blockIdx.x;
    int tid = threadIdx.x;

    for (int e = tid; e < W_ * 32; e += 256) {
        int i = e >> 5, j = e & 31;
        float s = 0.f;
#pragma unroll
        for (int sp = 0; sp < NSPLIT; sp++)
            s += g_part[(size_t)(sp * NROWS + b * W_ + i) * 32 + j];
        if (j < 16) sxr[i * 16 + j] = s;
        else        sxi[i * 16 + j - 16] = -s;   // rfft: imag = -sum(h*sin)
    }
    __syncthreads();

#pragma unroll
    for (int q = 0; q < 4; q++) {
        int item = tid + 256 * q;        // 1024 items: 64 o x 16 k
        int o = item >> 4;
        int k = item & 15;
        float accr = 0.f, acci = 0.f;
#pragma unroll
        for (int i = 0; i < W_; i++) {
            float xr = sxr[i * 16 + k], xi = sxi[i * 16 + k];
            float wrr = __ldg(&wr[((l * W_ + i) * W_ + o) * M_ + k]);
            float wii = __ldg(&wi[((l * W_ + i) * W_ + o) * M_ + k]);
            accr += xr * wrr - xi * wii;
            acci += xr * wii + xi * wrr;
        }
        float sc = (k == 0 ? 1.0f : 2.0f) / (float)S_;
        g_ar[(b * W_ + o) * M_ + k] = accr * sc;
        g_ai[(b * W_ + o) * M_ + k] = acci * sc;
    }
}

// ---------------------------------------------------------------
// layer update (in-place): h[b,o,s] = relu?( irfft16(of)[o,s] + pw conv + bias )
__global__ __launch_bounds__(256) void k_layer(
    const float* __restrict__ pw_w, const float* __restrict__ pw_b,
    int l, int do_relu)
{
    extern __shared__ float sm[];
    float* sh  = sm;                 // 64*128
    float* sF  = sh + 64 * 128;      // 128*33
    float* sW  = sF + 128 * 33;      // 64*64
    float* sar = sW + 64 * 64;       // 64*16
    float* sai = sar + 64 * 16;      // 64*16
    float* sb  = sai + 64 * 16;      // 64

    int b = blockIdx.y;
    int s0 = blockIdx.x * 128;
    int tid = threadIdx.x;
    int tx = tid & 31;   // s lane
    int ty = tid >> 5;   // o group (8)

    for (int e4 = tid; e4 < 64 * 32; e4 += 256) {       // 2048 float4
        int w = e4 >> 5, c4 = (e4 & 31) * 4;
        *(float4*)&sh[w * 128 + c4] =
            *(const float4*)&g_h[(size_t)(b * W_ + w) * S_ + s0 + c4];
    }
    for (int e = tid; e < 128 * 32; e += 256) {
        int s = e >> 5, j = e & 31;
        sF[s * 33 + j] = g_F[(s0 + s) * 32 + j];
    }
    for (int e4 = tid; e4 < 64 * 16; e4 += 256)
        *(float4*)&sW[e4 * 4] = *(const float4*)&pw_w[l * W_ * W_ + e4 * 4];
    // sar/sai: 64*16 = 1024 floats each = 256 float4 each
    for (int e4 = tid; e4 < (W_ * M_) / 4; e4 += 256) {
        *(float4*)&sar[e4 * 4] = *(const float4*)&g_ar[(b * W_) * M_ + e4 * 4];
        *(float4*)&sai[e4 * 4] = *(const float4*)&g_ai[(b * W_) * M_ + e4 * 4];
    }
    if (tid < 64) sb[tid] = pw_b[l * W_ + tid];
    __syncthreads();

    float acc[8][4];
#pragma unroll
    for (int r = 0; r < 8; r++)
#pragma unroll
        for (int c = 0; c < 4; c++) acc[r][c] = 0.f;

    // pointwise conv
#pragma unroll 4
    for (int i = 0; i < W_; i++) {
        float hv[4], wv[8];
#pragma unroll
        for (int c = 0; c < 4; c++) hv[c] = sh[i * 128 + tx + 32 * c];
#pragma unroll
        for (int r = 0; r < 8; r++) wv[r] = sW[(ty + 8 * r) * 64 + i];
#pragma unroll
        for (int r = 0; r < 8; r++)
#pragma unroll
            for (int c = 0; c < 4; c++) acc[r][c] += wv[r] * hv[c];
    }
    // irfft from 16 modes
#pragma unroll
    for (int k = 0; k < M_; k++) {
        float fc[4], fs[4], arr[8], aii[8];
#pragma unroll
        for (int c = 0; c < 4; c++) {
            fc[c] = sF[(tx + 32 * c) * 33 + k];
            fs[c] = sF[(tx + 32 * c) * 33 + 16 + k];
        }
#pragma unroll
        for (int r = 0; r < 8; r++) {
            arr[r] = sar[(ty + 8 * r) * 16 + k];
            aii[r] = sai[(ty + 8 * r) * 16 + k];
        }
#pragma unroll
        for (int r = 0; r < 8; r++)
#pragma unroll
            for (int c = 0; c < 4; c++)
                acc[r][c] += arr[r] * fc[c] - aii[r] * fs[c];
    }
#pragma unroll
    for (int r = 0; r < 8; r++) {
        int o = ty + 8 * r;
        float bo = sb[o];
#pragma unroll
        for (int c = 0; c < 4; c++) {
            float v = acc[r][c] + bo;
            if (do_relu) v = fmaxf(v, 0.f);
            g_h[(size_t)(b * W_ + o) * S_ + s0 + tx + 32 * c] = v;
        }
    }
}

// ---------------------------------------------------------------
// head: per (b, 128-wide s tile), 512 threads:
//   y = fc1_w @ h + fc1_b; U = relu(y)*fc2_w; tc = ica_w @ U + ica_b; out = sum_p tc
__global__ __launch_bounds__(512) void k_head(
    const float* __restrict__ fc1_w, const float* __restrict__ fc1_b,
    const float* __restrict__ fc2_w, const float* __restrict__ ica_w,
    const float* __restrict__ ica_b, float* __restrict__ out,
    float* __restrict__ tc)
{
    extern __shared__ float sm[];
    float* sh   = sm;                   // 64*128   = 8192
    float* sfc1 = sh + 64 * 128;        // 128*65   = 8320
    float* sU   = sfc1 + 128 * 65;      // 128*130  = 16640
    float* sica = sU + 128 * 130;       // 24*128   = 3072
    float* sTc  = sica + 24 * 128;      // 128*25   = 3200
    float* sb1  = sTc + 128 * 25;       // 128
    float* sf2  = sb1 + 128;            // 128
    float* sib  = sf2 + 128;            // 24
    __shared__ float sred[4][128];

    int b = blockIdx.y;
    int s0 = blockIdx.x * 128;
    int tid = threadIdx.x;

    for (int e4 = tid; e4 < 64 * 32; e4 += 512) {
        int w = e4 >> 5, c4 = (e4 & 31) * 4;
        *(float4*)&sh[w * 128 + c4] =
            *(const float4*)&g_h[(size_t)(b * W_ + w) * S_ + s0 + c4];
    }
    for (int e = tid; e < 128 * 64; e += 512) {
        int j = e >> 6, w = e & 63;
        sfc1[j * 65 + w] = fc1_w[e];
    }
    for (int e = tid; e < 24 * 128; e += 512) sica[e] = ica_w[e];
    if (tid < 128) { sb1[tid] = fc1_b[tid]; sf2[tid] = fc2_w[tid]; }
    if (tid >= 128 && tid < 152) sib[tid - 128] = ica_b[tid - 128];
    __syncthreads();

    // GEMM1: Y[128 j][128 s], thread tile 8j x 4s
    {
        int tx = tid & 31;    // s lane
        int ty = tid >> 5;    // j group, 0..15
        float acc[8][4];
#pragma unroll
        for (int r = 0; r < 8; r++)
#pragma unroll
            for (int c = 0; c < 4; c++) acc[r][c] = 0.f;
#pragma unroll 4
        for (int w = 0; w < 64; w++) {
            float hv[4], fv[8];
#pragma unroll
            for (int c = 0; c < 4; c++) hv[c] = sh[w * 128 + tx + 32 * c];
#pragma unroll
            for (int r = 0; r < 8; r++) fv[r] = sfc1[(ty + 16 * r) * 65 + w];
#pragma unroll
            for (int r = 0; r < 8; r++)
#pragma unroll
                for (int c = 0; c < 4; c++) acc[r][c] += fv[r] * hv[c];
        }
#pragma unroll
        for (int r = 0; r < 8; r++) {
            int j = ty + 16 * r;
            float bj = sb1[j], f2 = sf2[j];
#pragma unroll
            for (int c = 0; c < 4; c++)
                sU[j * 130 + tx + 32 * c] = fmaxf(acc[r][c] + bj, 0.f) * f2;
        }
    }
    __syncthreads();

    // GEMM2: tc[24 p][128 s]; thread: 1 s, 6 p (p = pq + 4q)
    {
        int s = tid & 127;
        int pq = tid >> 7;   // 0..3
        float a2[6];
#pragma unroll
        for (int q = 0; q < 6; q++) a2[q] = 0.f;
#pragma unroll 4
        for (int j = 0; j < 128; j++) {
            float uv = sU[j * 130 + s];
#pragma unroll
            for (int q = 0; q < 6; q++)
                a2[q] += sica[(pq + 4 * q) * 128 + j] * uv;
        }
        float psum = 0.f;
#pragma unroll
        for (int q = 0; q < 6; q++) {
            int p = pq + 4 * q;
            float v = a2[q] + sib[p];
            sTc[s * 25 + p] = v;
            psum += v;
        }
        sred[pq][s] = psum;
    }
    __syncthreads();

    float* tc_base = tc + (size_t)(b * S_ + s0) * P_;
    for (int e = tid; e < 128 * P_; e += 512) {
        int s = e / P_, p = e % P_;
        tc_base[e] = sTc[s * 25 + p];
    }
    if (tid < 128)
        out[(size_t)b * S_ + s0 + tid] =
            sred[0][tid] + sred[1][tid] + sred[2][tid] + sred[3][tid];
}

// ---------------------------------------------------------------
extern "C" void kernel_launch(void* const* d_in, const int* in_sizes, int n_in,
                              void* d_out, int out_size) {
    (void)in_sizes; (void)n_in; (void)out_size;
    const float* x       = (const float*)d_in[0];
    const float* fc0_w   = (const float*)d_in[1];
    const float* fc0_b   = (const float*)d_in[2];
    const float* conv_wr = (const float*)d_in[3];
    const float* conv_wi = (const float*)d_in[4];
    const float* pw_w    = (const float*)d_in[5];
    const float* pw_b    = (const float*)d_in[6];
    const float* fc1_w   = (const float*)d_in[7];
    const float* fc1_b   = (const float*)d_in[8];
    const float* fc2_w   = (const float*)d_in[9];
    const float* ica_w   = (const float*)d_in[10];
    const float* ica_b   = (const float*)d_in[11];

    float* out = (float*)d_out;
    float* tc  = out + (size_t)B_ * S_ * COUT_;

    const int LAY_SMEM  = (64*128 + 128*33 + 64*64 + 64*16*2 + 64) * 4;
    const int HEAD_SMEM = (64*128 + 128*65 + 128*130 + 24*128 + 128*25 + 280) * 4;
    cudaFuncSetAttribute(k_layer, cudaFuncAttributeMaxDynamicSharedMemorySize, LAY_SMEM);
    cudaFuncSetAttribute(k_head,  cudaFuncAttributeMaxDynamicSharedMemorySize, HEAD_SMEM);

    k_compute_F<<<(S_ * M_ + 255) / 256, 256>>>();
    k_lift<<<dim3(S_ / 256, B_), 256>>>(x, fc0_w, fc0_b);

    for (int l = 0; l < 4; l++) {
        k_dft_fwd<<<dim3(NROWS / DROWS, NSPLIT), 256>>>();
        k_specmul<<<B_, 256>>>(conv_wr, conv_wi, l);
        k_layer<<<dim3(S_ / 128, B_), 256, LAY_SMEM>>>(pw_w, pw_b, l, (l < 3) ? 1 : 0);
    }

    k_head<<<dim3(S_ / 128, B_), 512, HEAD_SMEM>>>(fc1_w, fc1_b, fc2_w, ica_w, ica_b, out, tc);
}

// round 8
// speedup vs baseline: 1.7382x; 1.2257x over previous
#include <cuda_runtime.h>
#include <math.h>

#define B_ 32
#define S_ 8192
#define CIN_ 2
#define COUT_ 1
#define W_ 64
#define M_ 16
#define P_ 24
#define NROWS (B_*W_)      /* 2048 */
#define NSPLIT 32

typedef unsigned long long u64;

// ---- f32x2 packed helpers ----
__device__ __forceinline__ u64 pack2(float a, float b) {
    u64 r; asm("mov.b64 %0, {%1,%2};" : "=l"(r) : "f"(a), "f"(b)); return r;
}
__device__ __forceinline__ u64 fma2(u64 a, u64 b, u64 c) {
    u64 d; asm("fma.rn.f32x2 %0, %1, %2, %3;" : "=l"(d) : "l"(a), "l"(b), "l"(c)); return d;
}
__device__ __forceinline__ float2 unpack2(u64 v) {
    float2 f; asm("mov.b64 {%0,%1}, %2;" : "=f"(f.x), "=f"(f.y) : "l"(v)); return f;
}

// -------- scratch (device globals; no allocation allowed) --------
__device__ float g_h[NROWS * S_];            // 64 MB
__device__ float g_F[S_ * 32];               // [s][j]: j<16 cos, j>=16 sin
__device__ float g_part[NSPLIT * NROWS * 32];// split-K partials (8 MB)
__device__ float g_xf[NROWS * 32];           // reduced DFT coeffs
__device__ float g_ar[B_ * W_ * M_];
__device__ float g_ai[B_ * W_ * M_];

// ---------------------------------------------------------------
__global__ void k_compute_F() {
    int idx = blockIdx.x * blockDim.x + threadIdx.x;
    if (idx >= S_ * M_) return;
    int s = idx / M_, k = idx % M_;
    int r = (s * k) % S_;
    float c, sn;
    sincospif((float)r / 4096.0f, &sn, &c);
    g_F[s * 32 + k]      = c;
    g_F[s * 32 + 16 + k] = sn;
}

// ---------------------------------------------------------------
__global__ __launch_bounds__(256) void k_lift(
    const float* __restrict__ x, const float* __restrict__ fc0_w,
    const float* __restrict__ fc0_b)
{
    int s = blockIdx.x * 256 + threadIdx.x;
    int b = blockIdx.y;
    float2 xv = *(const float2*)&x[(b * S_ + s) * 2];
#pragma unroll
    for (int w = 0; w < W_; w++) {
        float v = xv.x * __ldg(&fc0_w[w * 2]) + xv.y * __ldg(&fc0_w[w * 2 + 1]) + __ldg(&fc0_b[w]);
        g_h[(b * W_ + w) * S_ + s] = v;
    }
}

// ---------------------------------------------------------------
// fwd DFT split-K
#define KT 32
#define DROWS 256
__global__ __launch_bounds__(256) void k_dft_fwd() {
    __shared__ float sA[DROWS * 36];
    __shared__ float sB[KT * 32];
    int tid = threadIdx.x;
    int tx = tid & 7;
    int ty = tid >> 3;
    int row0 = blockIdx.x * DROWS;
    int split = blockIdx.y;

    float acc[8][4];
#pragma unroll
    for (int r = 0; r < 8; r++)
#pragma unroll
        for (int c = 0; c < 4; c++) acc[r][c] = 0.f;

    const int KSPLIT = S_ / NSPLIT;
    for (int kt = 0; kt < KSPLIT / KT; kt++) {
        int k0 = split * KSPLIT + kt * KT;
        {
            int c4 = (tid & 7) * 4;
            int rb = tid >> 3;
#pragma unroll
            for (int it = 0; it < 8; it++) {
                int row = rb + 32 * it;
                float4 v = *(const float4*)&g_h[(size_t)(row0 + row) * S_ + k0 + c4];
                *(float4*)&sA[row * 36 + c4] = v;
            }
        }
        {
            int j4 = (tid & 7) * 4;
            int kk = tid >> 3;
            *(float4*)&sB[kk * 32 + j4] = *(const float4*)&g_F[(k0 + kk) * 32 + j4];
        }
        __syncthreads();
#pragma unroll
        for (int kk = 0; kk < KT; kk++) {
            float a[8], bb[4];
#pragma unroll
            for (int r = 0; r < 8; r++) a[r] = sA[(ty + 32 * r) * 36 + kk];
#pragma unroll
            for (int c = 0; c < 4; c++) bb[c] = sB[kk * 32 + tx + 8 * c];
#pragma unroll
            for (int r = 0; r < 8; r++)
#pragma unroll
                for (int c = 0; c < 4; c++) acc[r][c] += a[r] * bb[c];
        }
        __syncthreads();
    }
#pragma unroll
    for (int r = 0; r < 8; r++)
#pragma unroll
        for (int c = 0; c < 4; c++)
            g_part[(size_t)(split * NROWS + row0 + ty + 32 * r) * 32 + tx + 8 * c] = acc[r][c];
}

// ---------------------------------------------------------------
// reduce split-K partials: g_xf[row][j] = sum_sp g_part[sp][row][j]
__global__ __launch_bounds__(256) void k_reduce() {
    int idx = blockIdx.x * 256 + threadIdx.x;   // 0..16383
    int row = idx >> 3;
    int c4 = (idx & 7) * 4;
    float4 s = make_float4(0.f, 0.f, 0.f, 0.f);
#pragma unroll
    for (int sp = 0; sp < NSPLIT; sp++) {
        float4 v = *(const float4*)&g_part[(size_t)(sp * NROWS + row) * 32 + c4];
        s.x += v.x; s.y += v.y; s.z += v.z; s.w += v.w;
    }
    *(float4*)&g_xf[row * 32 + c4] = s;
}

// ---------------------------------------------------------------
// spectral multiply: grid (B_, 4), 256 threads = 16 o x 16 k.
__global__ __launch_bounds__(256) void k_specmul(
    const float* __restrict__ wr, const float* __restrict__ wi, int l)
{
    __shared__ float sxr[W_ * 16];
    __shared__ float sxi[W_ * 16];
    int b = blockIdx.x;
    int o0 = blockIdx.y * 16;
    int tid = threadIdx.x;

    for (int e = tid; e < W_ * 32; e += 256) {
        int i = e >> 5, j = e & 31;
        float v = g_xf[(b * W_ + i) * 32 + j];
        if (j < 16) sxr[i * 16 + j] = v;
        else        sxi[i * 16 + j - 16] = -v;   // imag = -sum(h*sin)
    }
    __syncthreads();

    int o = o0 + (tid >> 4);
    int k = tid & 15;
    float accr = 0.f, acci = 0.f;
#pragma unroll
    for (int i = 0; i < W_; i++) {
        float xr = sxr[i * 16 + k], xi = sxi[i * 16 + k];
        float wrr = __ldg(&wr[((l * W_ + i) * W_ + o) * M_ + k]);
        float wii = __ldg(&wi[((l * W_ + i) * W_ + o) * M_ + k]);
        accr += xr * wrr - xi * wii;
        acci += xr * wii + xi * wrr;
    }
    float sc = (k == 0 ? 1.0f : 2.0f) / (float)S_;
    g_ar[(b * W_ + o) * M_ + k] = accr * sc;
    g_ai[(b * W_ + o) * M_ + k] = acci * sc;
}

// ---------------------------------------------------------------
// layer update, f32x2 packed over o-pairs.
__global__ __launch_bounds__(256) void k_layer(
    const float* __restrict__ pw_w, const float* __restrict__ pw_b,
    int l, int do_relu)
{
    extern __shared__ float sm[];
    float* sh    = sm;                  // 64*128   @0
    float* sF    = sh + 64 * 128;       // 128*33   @8192
    float* sWt   = sF + 128 * 33;       // 64*66    @12416 (even) [i][o]
    float* sar_t = sWt + 64 * 66;       // 16*66    @16640 (even) [k][o]
    float* sai_t = sar_t + 16 * 66;     // 16*66    @17696 (even) [k][o], NEGATED
    float* sb    = sai_t + 16 * 66;     // 64       @18752 (even)

    int b = blockIdx.y;
    int s0 = blockIdx.x * 128;
    int tid = threadIdx.x;
    int tx = tid & 31;
    int ty = tid >> 5;
    int o0 = ty * 8;

    for (int e4 = tid; e4 < 64 * 32; e4 += 256) {
        int w = e4 >> 5, c4 = (e4 & 31) * 4;
        *(float4*)&sh[w * 128 + c4] =
            *(const float4*)&g_h[(size_t)(b * W_ + w) * S_ + s0 + c4];
    }
    for (int e = tid; e < 128 * 32; e += 256) {
        int s = e >> 5, j = e & 31;
        sF[s * 33 + j] = g_F[(s0 + s) * 32 + j];
    }
    // transposed pointwise weights: sWt[i*66 + o] = pw[l][o][i]
    for (int e = tid; e < 64 * 64; e += 256) {
        int o = e >> 6, i = e & 63;
        sWt[i * 66 + o] = pw_w[l * W_ * W_ + e];
    }
    // transposed spectral coeffs: [k][o]; sai negated (folds irfft sign)
    for (int e = tid; e < W_ * M_; e += 256) {
        int o = e >> 4, k = e & 15;
        sar_t[k * 66 + o] =  g_ar[(b * W_ + o) * M_ + k];
        sai_t[k * 66 + o] = -g_ai[(b * W_ + o) * M_ + k];
    }
    if (tid < 64) sb[tid] = pw_b[l * W_ + tid];
    __syncthreads();

    u64 acc2[4][4];
#pragma unroll
    for (int rp = 0; rp < 4; rp++)
#pragma unroll
        for (int c = 0; c < 4; c++) acc2[rp][c] = 0ULL;

    // pointwise conv: 16 f32x2-FMA per i
#pragma unroll 4
    for (int i = 0; i < W_; i++) {
        u64 hd[4], wv2[4];
#pragma unroll
        for (int c = 0; c < 4; c++) {
            float hv = sh[i * 128 + tx + 32 * c];
            hd[c] = pack2(hv, hv);
        }
#pragma unroll
        for (int rp = 0; rp < 4; rp++)
            wv2[rp] = *(const u64*)&sWt[i * 66 + o0 + 2 * rp];
#pragma unroll
        for (int rp = 0; rp < 4; rp++)
#pragma unroll
            for (int c = 0; c < 4; c++)
                acc2[rp][c] = fma2(wv2[rp], hd[c], acc2[rp][c]);
    }
    // irfft from 16 modes
#pragma unroll
    for (int k = 0; k < M_; k++) {
        u64 fcd[4], fsd[4], ar2[4], ain2[4];
#pragma unroll
        for (int c = 0; c < 4; c++) {
            float fc = sF[(tx + 32 * c) * 33 + k];
            float fs = sF[(tx + 32 * c) * 33 + 16 + k];
            fcd[c] = pack2(fc, fc);
            fsd[c] = pack2(fs, fs);
        }
#pragma unroll
        for (int rp = 0; rp < 4; rp++) {
            ar2[rp]  = *(const u64*)&sar_t[k * 66 + o0 + 2 * rp];
            ain2[rp] = *(const u64*)&sai_t[k * 66 + o0 + 2 * rp];
        }
#pragma unroll
        for (int rp = 0; rp < 4; rp++)
#pragma unroll
            for (int c = 0; c < 4; c++) {
                acc2[rp][c] = fma2(ar2[rp],  fcd[c], acc2[rp][c]);
                acc2[rp][c] = fma2(ain2[rp], fsd[c], acc2[rp][c]);
            }
    }
#pragma unroll
    for (int rp = 0; rp < 4; rp++) {
        int oA = o0 + 2 * rp, oB = oA + 1;
        float bA = sb[oA], bB = sb[oB];
#pragma unroll
        for (int c = 0; c < 4; c++) {
            float2 v = unpack2(acc2[rp][c]);
            float vA = v.x + bA, vB = v.y + bB;
            if (do_relu) { vA = fmaxf(vA, 0.f); vB = fmaxf(vB, 0.f); }
            g_h[(size_t)(b * W_ + oA) * S_ + s0 + tx + 32 * c] = vA;
            g_h[(size_t)(b * W_ + oB) * S_ + s0 + tx + 32 * c] = vB;
        }
    }
}

// ---------------------------------------------------------------
// head, f32x2 packed.
__global__ __launch_bounds__(512) void k_head(
    const float* __restrict__ fc1_w, const float* __restrict__ fc1_b,
    const float* __restrict__ fc2_w, const float* __restrict__ ica_w,
    const float* __restrict__ ica_b, float* __restrict__ out,
    float* __restrict__ tc)
{
    extern __shared__ float sm[];
    float* sh     = sm;                    // 64*128   @0
    float* sfc1t  = sh + 64 * 128;         // 64*130   @8192  [w][j]
    float* sU     = sfc1t + 64 * 130;      // 128*130  @16512 [j][s]
    float* sica   = sU + 128 * 130;        // 24*128   @33152
    float* sTc    = sica + 24 * 128;       // 128*25   @36224
    float* sb1    = sTc + 128 * 25;        // 128
    float* sf2    = sb1 + 128;             // 128
    float* sib    = sf2 + 128;             // 24
    __shared__ float sred[4][128];

    int b = blockIdx.y;
    int s0 = blockIdx.x * 128;
    int tid = threadIdx.x;

    for (int e4 = tid; e4 < 64 * 32; e4 += 512) {
        int w = e4 >> 5, c4 = (e4 & 31) * 4;
        *(float4*)&sh[w * 128 + c4] =
            *(const float4*)&g_h[(size_t)(b * W_ + w) * S_ + s0 + c4];
    }
    // transposed fc1: sfc1t[w*130 + j] = fc1_w[j][w]
    for (int e = tid; e < 128 * 64; e += 512) {
        int j = e >> 6, w = e & 63;
        sfc1t[w * 130 + j] = fc1_w[e];
    }
    for (int e = tid; e < 24 * 128; e += 512) sica[e] = ica_w[e];
    if (tid < 128) { sb1[tid] = fc1_b[tid]; sf2[tid] = fc2_w[tid]; }
    if (tid >= 128 && tid < 152) sib[tid - 128] = ica_b[tid - 128];
    __syncthreads();

    // GEMM1: Y[128 j][128 s]; thread: j = ty*8+r (8 consecutive), s = tx+32c
    {
        int tx = tid & 31;
        int ty = tid >> 5;      // 0..15
        int j0 = ty * 8;
        u64 acc2[4][4];
#pragma unroll
        for (int rp = 0; rp < 4; rp++)
#pragma unroll
            for (int c = 0; c < 4; c++) acc2[rp][c] = 0ULL;
#pragma unroll 4
        for (int w = 0; w < 64; w++) {
            u64 hd[4], fv2[4];
#pragma unroll
            for (int c = 0; c < 4; c++) {
                float hv = sh[w * 128 + tx + 32 * c];
                hd[c] = pack2(hv, hv);
            }
#pragma unroll
            for (int rp = 0; rp < 4; rp++)
                fv2[rp] = *(const u64*)&sfc1t[w * 130 + j0 + 2 * rp];
#pragma unroll
            for (int rp = 0; rp < 4; rp++)
#pragma unroll
                for (int c = 0; c < 4; c++)
                    acc2[rp][c] = fma2(fv2[rp], hd[c], acc2[rp][c]);
        }
#pragma unroll
        for (int rp = 0; rp < 4; rp++) {
            int jA = j0 + 2 * rp, jB = jA + 1;
            float bA = sb1[jA], fA = sf2[jA];
            float bB = sb1[jB], fB = sf2[jB];
#pragma unroll
            for (int c = 0; c < 4; c++) {
                float2 v = unpack2(acc2[rp][c]);
                sU[jA * 130 + tx + 32 * c] = fmaxf(v.x + bA, 0.f) * fA;
                sU[jB * 130 + tx + 32 * c] = fmaxf(v.y + bB, 0.f) * fB;
            }
        }
    }
    __syncthreads();

    // GEMM2: tc[24 p][128 s]; thread: 1 s, 6 p; j packed in pairs.
    {
        int s = tid & 127;
        int pq = tid >> 7;   // 0..3
        u64 a2[6];
#pragma unroll
        for (int q = 0; q < 6; q++) a2[q] = 0ULL;
#pragma unroll 4
        for (int jp = 0; jp < 64; jp++) {
            u64 uv2 = pack2(sU[(2 * jp) * 130 + s], sU[(2 * jp + 1) * 130 + s]);
#pragma unroll
            for (int q = 0; q < 6; q++) {
                u64 wv = *(const u64*)&sica[(pq + 4 * q) * 128 + 2 * jp];
                a2[q] = fma2(wv, uv2, a2[q]);
            }
        }
        float psum = 0.f;
#pragma unroll
        for (int q = 0; q < 6; q++) {
            int p = pq + 4 * q;
            float2 f = unpack2(a2[q]);
            float v = f.x + f.y + sib[p];
            sTc[s * 25 + p] = v;
            psum += v;
        }
        sred[pq][s] = psum;
    }
    __syncthreads();

    float* tc_base = tc + (size_t)(b * S_ + s0) * P_;
    for (int e = tid; e < 128 * P_; e += 512) {
        int s = e / P_, p = e % P_;
        tc_base[e] = sTc[s * 25 + p];
    }
    if (tid < 128)
        out[(size_t)b * S_ + s0 + tid] =
            sred[0][tid] + sred[1][tid] + sred[2][tid] + sred[3][tid];
}

// ---------------------------------------------------------------
extern "C" void kernel_launch(void* const* d_in, const int* in_sizes, int n_in,
                              void* d_out, int out_size) {
    (void)in_sizes; (void)n_in; (void)out_size;
    const float* x       = (const float*)d_in[0];
    const float* fc0_w   = (const float*)d_in[1];
    const float* fc0_b   = (const float*)d_in[2];
    const float* conv_wr = (const float*)d_in[3];
    const float* conv_wi = (const float*)d_in[4];
    const float* pw_w    = (const float*)d_in[5];
    const float* pw_b    = (const float*)d_in[6];
    const float* fc1_w   = (const float*)d_in[7];
    const float* fc1_b   = (const float*)d_in[8];
    const float* fc2_w   = (const float*)d_in[9];
    const float* ica_w   = (const float*)d_in[10];
    const float* ica_b   = (const float*)d_in[11];

    float* out = (float*)d_out;
    float* tc  = out + (size_t)B_ * S_ * COUT_;

    const int LAY_SMEM  = (64*128 + 128*33 + 64*66 + 16*66*2 + 64) * 4;           // 75264 B
    const int HEAD_SMEM = (64*128 + 64*130 + 128*130 + 24*128 + 128*25 + 280) * 4; // 158816 B
    cudaFuncSetAttribute(k_layer, cudaFuncAttributeMaxDynamicSharedMemorySize, LAY_SMEM);
    cudaFuncSetAttribute(k_head,  cudaFuncAttributeMaxDynamicSharedMemorySize, HEAD_SMEM);

    k_compute_F<<<(S_ * M_ + 255) / 256, 256>>>();
    k_lift<<<dim3(S_ / 256, B_), 256>>>(x, fc0_w, fc0_b);

    for (int l = 0; l < 4; l++) {
        k_dft_fwd<<<dim3(NROWS / DROWS, NSPLIT), 256>>>();
        k_reduce<<<64, 256>>>();
        k_specmul<<<dim3(B_, 4), 256>>>(conv_wr, conv_wi, l);
        k_layer<<<dim3(S_ / 128, B_), 256, LAY_SMEM>>>(pw_w, pw_b, l, (l < 3) ? 1 : 0);
    }

    k_head<<<dim3(S_ / 128, B_), 512, HEAD_SMEM>>>(fc1_w, fc1_b, fc2_w, ica_w, ica_b, out, tc);
}

// round 10
// speedup vs baseline: 1.7781x; 1.0229x over previous
#include <cuda_runtime.h>
#include <math.h>

#define B_ 32
#define S_ 8192
#define CIN_ 2
#define COUT_ 1
#define W_ 64
#define M_ 16
#define P_ 24
#define NROWS (B_*W_)      /* 2048 */
#define NSPLIT 32

typedef unsigned long long u64;

// ---- f32x2 packed helpers ----
__device__ __forceinline__ u64 pack2(float a, float b) {
    u64 r; asm("mov.b64 %0, {%1,%2};" : "=l"(r) : "f"(a), "f"(b)); return r;
}
__device__ __forceinline__ u64 fma2(u64 a, u64 b, u64 c) {
    u64 d; asm("fma.rn.f32x2 %0, %1, %2, %3;" : "=l"(d) : "l"(a), "l"(b), "l"(c)); return d;
}
__device__ __forceinline__ float2 unpack2(u64 v) {
    float2 f; asm("mov.b64 {%0,%1}, %2;" : "=f"(f.x), "=f"(f.y) : "l"(v)); return f;
}

// -------- scratch (device globals; no allocation allowed) --------
__device__ float g_h[NROWS * S_];            // 64 MB
__device__ float g_F[S_ * 32];               // [s][j]: j<16 cos, j>=16 sin
__device__ float g_part[NSPLIT * NROWS * 32];// split-K partials (8 MB)
__device__ float g_xf[NROWS * 32];           // reduced DFT coeffs
__device__ float g_ar[B_ * W_ * M_];
__device__ float g_ai[B_ * W_ * M_];

// ---------------------------------------------------------------
__global__ void k_compute_F() {
    int idx = blockIdx.x * blockDim.x + threadIdx.x;
    if (idx >= S_ * M_) return;
    int s = idx / M_, k = idx % M_;
    int r = (s * k) % S_;
    float c, sn;
    sincospif((float)r / 4096.0f, &sn, &c);
    g_F[s * 32 + k]      = c;
    g_F[s * 32 + 16 + k] = sn;
}

// ---------------------------------------------------------------
__global__ __launch_bounds__(256) void k_lift(
    const float* __restrict__ x, const float* __restrict__ fc0_w,
    const float* __restrict__ fc0_b)
{
    int s = blockIdx.x * 256 + threadIdx.x;
    int b = blockIdx.y;
    float2 xv = *(const float2*)&x[(b * S_ + s) * 2];
#pragma unroll
    for (int w = 0; w < W_; w++) {
        float v = xv.x * __ldg(&fc0_w[w * 2]) + xv.y * __ldg(&fc0_w[w * 2 + 1]) + __ldg(&fc0_b[w]);
        g_h[(b * W_ + w) * S_ + s] = v;
    }
}

// ---------------------------------------------------------------
// fwd DFT split-K, f32x2 packed over j-pairs.
// thread: ty = tid>>3 (rows ty+32r), txj = tid&7 (4 consecutive j = txj*4..+3).
#define KT 32
#define DROWS 256
__global__ __launch_bounds__(256) void k_dft_fwd() {
    __shared__ float sA[DROWS * 36];
    __shared__ float sB[KT * 32];
    int tid = threadIdx.x;
    int txj = tid & 7;       // j quad
    int ty = tid >> 3;       // row group, 0..31
    int row0 = blockIdx.x * DROWS;
    int split = blockIdx.y;

    u64 acc2[8][2];
#pragma unroll
    for (int r = 0; r < 8; r++) { acc2[r][0] = 0ULL; acc2[r][1] = 0ULL; }

    const int KSPLIT = S_ / NSPLIT;
    for (int kt = 0; kt < KSPLIT / KT; kt++) {
        int k0 = split * KSPLIT + kt * KT;
        {
            int c4 = (tid & 7) * 4;
            int rb = tid >> 3;
#pragma unroll
            for (int it = 0; it < 8; it++) {
                int row = rb + 32 * it;
                float4 v = *(const float4*)&g_h[(size_t)(row0 + row) * S_ + k0 + c4];
                *(float4*)&sA[row * 36 + c4] = v;
            }
        }
        {
            int j4 = (tid & 7) * 4;
            int kk = tid >> 3;
            *(float4*)&sB[kk * 32 + j4] = *(const float4*)&g_F[(k0 + kk) * 32 + j4];
        }
        __syncthreads();
#pragma unroll
        for (int kk = 0; kk < KT; kk++) {
            u64 b0 = *(const u64*)&sB[kk * 32 + txj * 4];
            u64 b1 = *(const u64*)&sB[kk * 32 + txj * 4 + 2];
#pragma unroll
            for (int r = 0; r < 8; r++) {
                float a = sA[(ty + 32 * r) * 36 + kk];
                u64 ad = pack2(a, a);
                acc2[r][0] = fma2(b0, ad, acc2[r][0]);
                acc2[r][1] = fma2(b1, ad, acc2[r][1]);
            }
        }
        __syncthreads();
    }
#pragma unroll
    for (int r = 0; r < 8; r++) {
        float2 lo = unpack2(acc2[r][0]);
        float2 hi = unpack2(acc2[r][1]);
        *(float4*)&g_part[(size_t)(split * NROWS + row0 + ty + 32 * r) * 32 + txj * 4] =
            make_float4(lo.x, lo.y, hi.x, hi.y);
    }
}

// ---------------------------------------------------------------
// reduce split-K partials: g_xf[row][j] = sum_sp g_part[sp][row][j]
__global__ __launch_bounds__(256) void k_reduce() {
    int idx = blockIdx.x * 256 + threadIdx.x;   // 0..16383
    int row = idx >> 3;
    int c4 = (idx & 7) * 4;
    float4 s = make_float4(0.f, 0.f, 0.f, 0.f);
#pragma unroll
    for (int sp = 0; sp < NSPLIT; sp++) {
        float4 v = *(const float4*)&g_part[(size_t)(sp * NROWS + row) * 32 + c4];
        s.x += v.x; s.y += v.y; s.z += v.z; s.w += v.w;
    }
    *(float4*)&g_xf[row * 32 + c4] = s;
}

// ---------------------------------------------------------------
// spectral multiply: grid (B_, 4), 256 threads = 16 o x 16 k.
__global__ __launch_bounds__(256) void k_specmul(
    const float* __restrict__ wr, const float* __restrict__ wi, int l)
{
    __shared__ float sxr[W_ * 16];
    __shared__ float sxi[W_ * 16];
    int b = blockIdx.x;
    int o0 = blockIdx.y * 16;
    int tid = threadIdx.x;

    for (int e = tid; e < W_ * 32; e += 256) {
        int i = e >> 5, j = e & 31;
        float v = g_xf[(b * W_ + i) * 32 + j];
        if (j < 16) sxr[i * 16 + j] = v;
        else        sxi[i * 16 + j - 16] = -v;   // imag = -sum(h*sin)
    }
    __syncthreads();

    int o = o0 + (tid >> 4);
    int k = tid & 15;
    float accr = 0.f, acci = 0.f;
#pragma unroll
    for (int i = 0; i < W_; i++) {
        float xr = sxr[i * 16 + k], xi = sxi[i * 16 + k];
        float wrr = __ldg(&wr[((l * W_ + i) * W_ + o) * M_ + k]);
        float wii = __ldg(&wi[((l * W_ + i) * W_ + o) * M_ + k]);
        accr += xr * wrr - xi * wii;
        acci += xr * wii + xi * wrr;
    }
    float sc = (k == 0 ? 1.0f : 2.0f) / (float)S_;
    g_ar[(b * W_ + o) * M_ + k] = accr * sc;
    g_ai[(b * W_ + o) * M_ + k] = acci * sc;
}

// ---------------------------------------------------------------
// layer update, f32x2 packed over o-pairs.
__global__ __launch_bounds__(256) void k_layer(
    const float* __restrict__ pw_w, const float* __restrict__ pw_b,
    int l, int do_relu)
{
    extern __shared__ float sm[];
    float* sh    = sm;                  // 64*128   @0
    float* sF    = sh + 64 * 128;       // 128*33   @8192
    float* sWt   = sF + 128 * 33;       // 64*66    @12416 (even) [i][o]
    float* sar_t = sWt + 64 * 66;       // 16*66    @16640 (even) [k][o]
    float* sai_t = sar_t + 16 * 66;     // 16*66    @17696 (even) [k][o], NEGATED
    float* sb    = sai_t + 16 * 66;     // 64       @18752 (even)

    int b = blockIdx.y;
    int s0 = blockIdx.x * 128;
    int tid = threadIdx.x;
    int tx = tid & 31;
    int ty = tid >> 5;
    int o0 = ty * 8;

    for (int e4 = tid; e4 < 64 * 32; e4 += 256) {
        int w = e4 >> 5, c4 = (e4 & 31) * 4;
        *(float4*)&sh[w * 128 + c4] =
            *(const float4*)&g_h[(size_t)(b * W_ + w) * S_ + s0 + c4];
    }
    for (int e = tid; e < 128 * 32; e += 256) {
        int s = e >> 5, j = e & 31;
        sF[s * 33 + j] = g_F[(s0 + s) * 32 + j];
    }
    // transposed pointwise weights: sWt[i*66 + o] = pw[l][o][i]
    for (int e = tid; e < 64 * 64; e += 256) {
        int o = e >> 6, i = e & 63;
        sWt[i * 66 + o] = pw_w[l * W_ * W_ + e];
    }
    // transposed spectral coeffs: [k][o]; sai negated (folds irfft sign)
    for (int e = tid; e < W_ * M_; e += 256) {
        int o = e >> 4, k = e & 15;
        sar_t[k * 66 + o] =  g_ar[(b * W_ + o) * M_ + k];
        sai_t[k * 66 + o] = -g_ai[(b * W_ + o) * M_ + k];
    }
    if (tid < 64) sb[tid] = pw_b[l * W_ + tid];
    __syncthreads();

    u64 acc2[4][4];
#pragma unroll
    for (int rp = 0; rp < 4; rp++)
#pragma unroll
        for (int c = 0; c < 4; c++) acc2[rp][c] = 0ULL;

    // pointwise conv: 16 f32x2-FMA per i
#pragma unroll 4
    for (int i = 0; i < W_; i++) {
        u64 hd[4], wv2[4];
#pragma unroll
        for (int c = 0; c < 4; c++) {
            float hv = sh[i * 128 + tx + 32 * c];
            hd[c] = pack2(hv, hv);
        }
#pragma unroll
        for (int rp = 0; rp < 4; rp++)
            wv2[rp] = *(const u64*)&sWt[i * 66 + o0 + 2 * rp];
#pragma unroll
        for (int rp = 0; rp < 4; rp++)
#pragma unroll
            for (int c = 0; c < 4; c++)
                acc2[rp][c] = fma2(wv2[rp], hd[c], acc2[rp][c]);
    }
    // irfft from 16 modes
#pragma unroll
    for (int k = 0; k < M_; k++) {
        u64 fcd[4], fsd[4], ar2[4], ain2[4];
#pragma unroll
        for (int c = 0; c < 4; c++) {
            float fc = sF[(tx + 32 * c) * 33 + k];
            float fs = sF[(tx + 32 * c) * 33 + 16 + k];
            fcd[c] = pack2(fc, fc);
            fsd[c] = pack2(fs, fs);
        }
#pragma unroll
        for (int rp = 0; rp < 4; rp++) {
            ar2[rp]  = *(const u64*)&sar_t[k * 66 + o0 + 2 * rp];
            ain2[rp] = *(const u64*)&sai_t[k * 66 + o0 + 2 * rp];
        }
#pragma unroll
        for (int rp = 0; rp < 4; rp++)
#pragma unroll
            for (int c = 0; c < 4; c++) {
                acc2[rp][c] = fma2(ar2[rp],  fcd[c], acc2[rp][c]);
                acc2[rp][c] = fma2(ain2[rp], fsd[c], acc2[rp][c]);
            }
    }
#pragma unroll
    for (int rp = 0; rp < 4; rp++) {
        int oA = o0 + 2 * rp, oB = oA + 1;
        float bA = sb[oA], bB = sb[oB];
#pragma unroll
        for (int c = 0; c < 4; c++) {
            float2 v = unpack2(acc2[rp][c]);
            float vA = v.x + bA, vB = v.y + bB;
            if (do_relu) { vA = fmaxf(vA, 0.f); vB = fmaxf(vB, 0.f); }
            g_h[(size_t)(b * W_ + oA) * S_ + s0 + tx + 32 * c] = vA;
            g_h[(size_t)(b * W_ + oB) * S_ + s0 + tx + 32 * c] = vB;
        }
    }
}

// ---------------------------------------------------------------
// head, f32x2 packed; sU stored s-major [s][j] so GEMM2 loads j-pairs as u64.
__global__ __launch_bounds__(512) void k_head(
    const float* __restrict__ fc1_w, const float* __restrict__ fc1_b,
    const float* __restrict__ fc2_w, const float* __restrict__ ica_w,
    const float* __restrict__ ica_b, float* __restrict__ out,
    float* __restrict__ tc)
{
    extern __shared__ float sm[];
    float* sh     = sm;                    // 64*128   @0
    float* sfc1t  = sh + 64 * 128;         // 64*130   @8192  [w][j]
    float* sU     = sfc1t + 64 * 130;      // 128*130  @16512 [s][j]
    float* sica   = sU + 128 * 130;        // 24*128   @33152
    float* sTc    = sica + 24 * 128;       // 128*25   @36224
    float* sb1    = sTc + 128 * 25;        // 128
    float* sf2    = sb1 + 128;             // 128
    float* sib    = sf2 + 128;             // 24
    __shared__ float sred[4][128];

    int b = blockIdx.y;
    int s0 = blockIdx.x * 128;
    int tid = threadIdx.x;

    for (int e4 = tid; e4 < 64 * 32; e4 += 512) {
        int w = e4 >> 5, c4 = (e4 & 31) * 4;
        *(float4*)&sh[w * 128 + c4] =
            *(const float4*)&g_h[(size_t)(b * W_ + w) * S_ + s0 + c4];
    }
    // transposed fc1: sfc1t[w*130 + j] = fc1_w[j][w]
    for (int e = tid; e < 128 * 64; e += 512) {
        int j = e >> 6, w = e & 63;
        sfc1t[w * 130 + j] = fc1_w[e];
    }
    for (int e = tid; e < 24 * 128; e += 512) sica[e] = ica_w[e];
    if (tid < 128) { sb1[tid] = fc1_b[tid]; sf2[tid] = fc2_w[tid]; }
    if (tid >= 128 && tid < 152) sib[tid - 128] = ica_b[tid - 128];
    __syncthreads();

    // GEMM1: Y[128 j][128 s]; thread: j = ty*8+r, s = tx+32c; store u64 into sU[s][j]
    {
        int tx = tid & 31;
        int ty = tid >> 5;      // 0..15
        int j0 = ty * 8;
        u64 acc2[4][4];
#pragma unroll
        for (int rp = 0; rp < 4; rp++)
#pragma unroll
            for (int c = 0; c < 4; c++) acc2[rp][c] = 0ULL;
#pragma unroll 4
        for (int w = 0; w < 64; w++) {
            u64 hd[4], fv2[4];
#pragma unroll
            for (int c = 0; c < 4; c++) {
                float hv = sh[w * 128 + tx + 32 * c];
                hd[c] = pack2(hv, hv);
            }
#pragma unroll
            for (int rp = 0; rp < 4; rp++)
                fv2[rp] = *(const u64*)&sfc1t[w * 130 + j0 + 2 * rp];
#pragma unroll
            for (int rp = 0; rp < 4; rp++)
#pragma unroll
                for (int c = 0; c < 4; c++)
                    acc2[rp][c] = fma2(fv2[rp], hd[c], acc2[rp][c]);
        }
#pragma unroll
        for (int rp = 0; rp < 4; rp++) {
            int jA = j0 + 2 * rp, jB = jA + 1;
            float bA = sb1[jA], fA = sf2[jA];
            float bB = sb1[jB], fB = sf2[jB];
#pragma unroll
            for (int c = 0; c < 4; c++) {
                float2 v = unpack2(acc2[rp][c]);
                float uA = fmaxf(v.x + bA, 0.f) * fA;
                float uB = fmaxf(v.y + bB, 0.f) * fB;
                *(u64*)&sU[(tx + 32 * c) * 130 + jA] = pack2(uA, uB);
            }
        }
    }
    __syncthreads();

    // GEMM2: tc[24 p][128 s]; thread: 1 s, 6 p; j-pairs via single LDS.64.
    {
        int s = tid & 127;
        int pq = tid >> 7;   // 0..3
        u64 a2[6];
#pragma unroll
        for (int q = 0; q < 6; q++) a2[q] = 0ULL;
#pragma unroll 4
        for (int jp = 0; jp < 64; jp++) {
            u64 uv2 = *(const u64*)&sU[s * 130 + 2 * jp];
#pragma unroll
            for (int q = 0; q < 6; q++) {
                u64 wv = *(const u64*)&sica[(pq + 4 * q) * 128 + 2 * jp];
                a2[q] = fma2(wv, uv2, a2[q]);
            }
        }
        float psum = 0.f;
#pragma unroll
        for (int q = 0; q < 6; q++) {
            int p = pq + 4 * q;
            float2 f = unpack2(a2[q]);
            float v = f.x + f.y + sib[p];
            sTc[s * 25 + p] = v;
            psum += v;
        }
        sred[pq][s] = psum;
    }
    __syncthreads();

    float* tc_base = tc + (size_t)(b * S_ + s0) * P_;
    for (int e = tid; e < 128 * P_; e += 512) {
        int s = e / P_, p = e % P_;
        tc_base[e] = sTc[s * 25 + p];
    }
    if (tid < 128)
        out[(size_t)b * S_ + s0 + tid] =
            sred[0][tid] + sred[1][tid] + sred[2][tid] + sred[3][tid];
}

// ---------------------------------------------------------------
extern "C" void kernel_launch(void* const* d_in, const int* in_sizes, int n_in,
                              void* d_out, int out_size) {
    (void)in_sizes; (void)n_in; (void)out_size;
    const float* x       = (const float*)d_in[0];
    const float* fc0_w   = (const float*)d_in[1];
    const float* fc0_b   = (const float*)d_in[2];
    const float* conv_wr = (const float*)d_in[3];
    const float* conv_wi = (const float*)d_in[4];
    const float* pw_w    = (const float*)d_in[5];
    const float* pw_b    = (const float*)d_in[6];
    const float* fc1_w   = (const float*)d_in[7];
    const float* fc1_b   = (const float*)d_in[8];
    const float* fc2_w   = (const float*)d_in[9];
    const float* ica_w   = (const float*)d_in[10];
    const float* ica_b   = (const float*)d_in[11];

    float* out = (float*)d_out;
    float* tc  = out + (size_t)B_ * S_ * COUT_;

    const int LAY_SMEM  = (64*128 + 128*33 + 64*66 + 16*66*2 + 64) * 4;           // 75264 B
    const int HEAD_SMEM = (64*128 + 64*130 + 128*130 + 24*128 + 128*25 + 280) * 4; // 158816 B
    cudaFuncSetAttribute(k_layer, cudaFuncAttributeMaxDynamicSharedMemorySize, LAY_SMEM);
    cudaFuncSetAttribute(k_head,  cudaFuncAttributeMaxDynamicSharedMemorySize, HEAD_SMEM);

    k_compute_F<<<(S_ * M_ + 255) / 256, 256>>>();
    k_lift<<<dim3(S_ / 256, B_), 256>>>(x, fc0_w, fc0_b);

    for (int l = 0; l < 4; l++) {
        k_dft_fwd<<<dim3(NROWS / DROWS, NSPLIT), 256>>>();
        k_reduce<<<64, 256>>>();
        k_specmul<<<dim3(B_, 4), 256>>>(conv_wr, conv_wi, l);
        k_layer<<<dim3(S_ / 128, B_), 256, LAY_SMEM>>>(pw_w, pw_b, l, (l < 3) ? 1 : 0);
    }

    k_head<<<dim3(S_ / 128, B_), 512, HEAD_SMEM>>>(fc1_w, fc1_b, fc2_w, ica_w, ica_b, out, tc);
}